// round 10
// baseline (speedup 1.0000x reference)
#include <cuda_runtime.h>

// PINN via tabulated jets. Quad-cooperative interpolation from a SHARED-
// memory table (32.8KB, 513 nodes, h=2^-9), persistent grid, phase-batched
// loads. Kernel A: order-6 jets (fp32, MUFU tanh). Kernel B: 4 lanes per
// point; one LDS.128 per lane fetches the node group; each lane emits 2 of
// the 8 outputs (2nd-order Taylor).
// Outputs: [u,u_x,u_xx,w,w_x,w_xx,w_xxx,w_xxxx].

#define KNODES 513
#define HINV   512.0f
#define HF     0.001953125f      // 2^-9 exact
#define MAGIC  12582912.0f       // 1.5 * 2^23

// node j: g0=(u0,u1,u2,u3) g1=(u3,u4,w0,w1) g2=(w1,w2,w3,w4) g3=(w3,w4,w5,w6)
__device__ float4 g_table4[KNODES * 4];

__device__ __forceinline__ float tanh_fast(float z, float& s) {
    float e, r;
    asm("ex2.approx.f32 %0, %1;" : "=f"(e) : "f"(z * 2.8853900817779268f));
    asm("rcp.approx.f32 %0, %1;" : "=f"(r) : "f"(e + 1.0f));
    float t = fmaf(-2.0f, r, 1.0f);
    s = fmaf(-t, t, 1.0f);
    return t;
}

// ---------------- Kernel A: order-6 jets at nodes ----------------

__global__ void pinn_build_table(const float* __restrict__ gW0, const float* __restrict__ gb0,
                                 const float* __restrict__ gW1, const float* __restrict__ gb1,
                                 const float* __restrict__ gW2, const float* __restrict__ gb2)
{
    int j = blockIdx.x * blockDim.x + threadIdx.x;
    if (j >= KNODES) return;

    const float x0 = (float)j * HF;

    float h[7][8];
#pragma unroll
    for (int k = 0; k < 8; ++k) {
        float w = gW0[k];
        float z = fmaf(w, x0, gb0[k]);
        float s;
        float t = tanh_fast(z, s);
        float t2 = t * t;
        float d2 = -2.0f * t * s;
        float d3 = s * (6.0f * t2 - 2.0f);
        float d4 = t * s * (16.0f - 24.0f * t2);
        float d5 = s * (16.0f + t2 * (-120.0f + 120.0f * t2));
        float d6 = s * t * (-272.0f + t2 * (960.0f - 720.0f * t2));
        float w2 = w * w, w3 = w2 * w;
        h[0][k] = t;
        h[1][k] = s  * w;
        h[2][k] = d2 * w2;
        h[3][k] = d3 * w3;
        h[4][k] = d4 * w2 * w2;
        h[5][k] = d5 * w2 * w3;
        h[6][k] = d6 * w3 * w3;
    }

    float u[5]; float wv[7];
    u[0] = gb2[0]; u[1] = u[2] = u[3] = u[4] = 0.0f;
    wv[0] = gb2[1];
#pragma unroll
    for (int m = 1; m < 7; ++m) wv[m] = 0.0f;

    for (int jn = 0; jn < 8; ++jn) {
        float z[7];
        z[0] = gb1[jn];
#pragma unroll
        for (int m = 1; m < 7; ++m) z[m] = 0.0f;
        for (int k = 0; k < 8; ++k) {
            float w = gW1[jn * 8 + k];
#pragma unroll
            for (int m = 0; m < 7; ++m) z[m] = fmaf(w, h[m][k], z[m]);
        }
        float s;
        float t = tanh_fast(z[0], s);
        float t2 = t * t;
        float d1 = s;
        float d2 = -2.0f * t * s;
        float d3 = s * (6.0f * t2 - 2.0f);
        float d4 = t * s * (16.0f - 24.0f * t2);
        float d5 = s * (16.0f + t2 * (-120.0f + 120.0f * t2));
        float d6 = s * t * (-272.0f + t2 * (960.0f - 720.0f * t2));

        float z1 = z[1], z2 = z[2], z3 = z[3], z4 = z[4], z5 = z[5], z6 = z[6];
        float z1_2 = z1 * z1, z1_3 = z1_2 * z1, z1_4 = z1_2 * z1_2;
        float g[7];
        g[0] = t;
        g[1] = d1 * z1;
        g[2] = d1 * z2 + d2 * z1_2;
        g[3] = d1 * z3 + 3.0f * d2 * z1 * z2 + d3 * z1_3;
        g[4] = d1 * z4 + d2 * (4.0f * z1 * z3 + 3.0f * z2 * z2)
             + 6.0f * d3 * z1_2 * z2 + d4 * z1_4;
        g[5] = d1 * z5 + d2 * (5.0f * z1 * z4 + 10.0f * z2 * z3)
             + d3 * (10.0f * z1_2 * z3 + 15.0f * z1 * z2 * z2)
             + 10.0f * d4 * z1_3 * z2 + d5 * z1_4 * z1;
        g[6] = d1 * z6 + d2 * (6.0f * z1 * z5 + 15.0f * z2 * z4 + 10.0f * z3 * z3)
             + d3 * (15.0f * z1_2 * z4 + 60.0f * z1 * z2 * z3 + 15.0f * z2 * z2 * z2)
             + d4 * (20.0f * z1_3 * z3 + 45.0f * z1_2 * z2 * z2)
             + 15.0f * d5 * z1_4 * z2 + d6 * z1_4 * z1_2;

        float wu = gW2[jn];
        float ww = gW2[8 + jn];
#pragma unroll
        for (int m = 0; m < 5; ++m) u[m]  = fmaf(wu, g[m], u[m]);
#pragma unroll
        for (int m = 0; m < 7; ++m) wv[m] = fmaf(ww, g[m], wv[m]);
    }

    float4* tb = &g_table4[j * 4];
    tb[0] = make_float4(u[0],  u[1],  u[2],  u[3]);
    tb[1] = make_float4(u[3],  u[4],  wv[0], wv[1]);
    tb[2] = make_float4(wv[1], wv[2], wv[3], wv[4]);
    tb[3] = make_float4(wv[3], wv[4], wv[5], wv[6]);
}

// ---------------- Kernel B: persistent, smem table, quad-cooperative ----

#define IB     512
#define IGRID  592                       // 4 blocks/SM * 148
#define TW     ((IGRID * IB) / 32)       // total warps = 9472
#define PPQ    4
#define SMEM_BYTES (KNODES * 4 * 16)     // 32832

__global__ __launch_bounds__(IB, 4)
void pinn_interp(const float* __restrict__ x, float* __restrict__ out, int n)
{
    extern __shared__ __align__(16) float4 s_tbl4[];   // [KNODES*4]

    // stage table into shared (32.8KB)
    for (int idx = threadIdx.x; idx < KNODES * 4; idx += IB)
        s_tbl4[idx] = g_table4[idx];
    __syncthreads();

    const int lane = threadIdx.x & 31;
    const int sub  = lane & 3;
    const int lb   = lane & ~3;
    const int quad = lane >> 2;                         // 0..7
    const int wid  = (blockIdx.x * IB + threadIdx.x) >> 5;

    for (int chunk = wid; chunk * 32 < n; chunk += TW) {
        const int wbase = chunk * 32;

        // ---- Phase 1: batched x loads ----
        float xv[PPQ];
#pragma unroll
        for (int k = 0; k < PPQ; ++k) {
            int p  = wbase + 8 * k + quad;
            int pc = p < n ? p : n - 1;
            xv[k] = __ldg(x + pc);
        }

        // ---- Phase 2: index math + batched smem table loads ----
        int   jn[PPQ];
        float dx[PPQ], t2[PPQ];
#pragma unroll
        for (int k = 0; k < PPQ; ++k) {
            float tm = fmaf(xv[k], HINV, MAGIC);
            jn[k] = __float_as_int(tm) & 0xFFFF;
            float fj = tm - MAGIC;
            dx[k] = fmaf(fj, -HF, xv[k]);
            t2[k] = 0.5f * dx[k] * dx[k];
        }
        float4 f[PPQ];
#pragma unroll
        for (int k = 0; k < PPQ; ++k)
            f[k] = s_tbl4[jn[k] * 4 + sub];

        // ---- Phase 3: seam shuffles, Taylor, coalesced stores ----
#pragma unroll
        for (int k = 0; k < PPQ; ++k) {
            float sz = __shfl_sync(0xffffffffu, f[k].z, lb);      // u2 from sub0
            float sy = __shfl_sync(0xffffffffu, f[k].y, lb + 2);  // w2 from sub2

            float oA, oB;
            if (sub == 1) {
                oA = fmaf(t2[k], f[k].y, fmaf(dx[k], f[k].x, sz));     // u_xx
                oB = fmaf(t2[k], sy,     fmaf(dx[k], f[k].w, f[k].z)); // w
            } else {
                oA = fmaf(t2[k], f[k].z, fmaf(dx[k], f[k].y, f[k].x));
                oB = fmaf(t2[k], f[k].w, fmaf(dx[k], f[k].z, f[k].y));
            }

            int p = wbase + 8 * k + quad;
            if (p < n) {
                float2* op = reinterpret_cast<float2*>(out + (size_t)p * 8) + sub;
                *op = make_float2(oA, oB);
            }
        }
    }
}

extern "C" void kernel_launch(void* const* d_in, const int* in_sizes, int n_in,
                              void* d_out, int out_size)
{
    const float* x  = (const float*)d_in[0];
    const float* W0 = (const float*)d_in[1];
    const float* b0 = (const float*)d_in[2];
    const float* W1 = (const float*)d_in[3];
    const float* b1 = (const float*)d_in[4];
    const float* W2 = (const float*)d_in[5];
    const float* b2 = (const float*)d_in[6];
    float* out = (float*)d_out;

    int n = in_sizes[0];

    cudaFuncSetAttribute(pinn_interp,
                         cudaFuncAttributeMaxDynamicSharedMemorySize, SMEM_BYTES);

    pinn_build_table<<<(KNODES + 127) / 128, 128>>>(W0, b0, W1, b1, W2, b2);
    pinn_interp<<<IGRID, IB, SMEM_BYTES>>>(x, out, n);
}

// round 11
// speedup vs baseline: 1.2168x; 1.2168x over previous
#include <cuda_runtime.h>

// PINN via tabulated jets, octet-cooperative interpolation.
// Table: 513 nodes (h=2^-9), each node 128B = 8 float4 groups, group s =
// (val, d1, d2, pad) for output s in [u,u_x,u_xx,w,w_x,w_xx,w_xxx,w_xxxx].
// Kernel A: order-6 jets, 8 threads/node (one per layer-1 neuron), shuffles.
// Kernel B: 8 lanes per point, one LDG.128 per lane = whole node line,
// 2 FMAs per lane, coalesced STG.32. No shuffles on the hot path.

#define KNODES 513
#define HINV   512.0f
#define HF     0.001953125f      // 2^-9 exact
#define MAGIC  12582912.0f       // 1.5 * 2^23

__device__ __align__(128) float4 g_tab8[KNODES * 8];

__device__ __forceinline__ float tanh_fast(float z, float& s) {
    float e, r;
    asm("ex2.approx.f32 %0, %1;" : "=f"(e) : "f"(z * 2.8853900817779268f));
    asm("rcp.approx.f32 %0, %1;" : "=f"(r) : "f"(e + 1.0f));
    float t = fmaf(-2.0f, r, 1.0f);
    s = fmaf(-t, t, 1.0f);
    return t;
}

// ---------------- Kernel A: order-6 jets, 8 threads per node ----------------

__global__ __launch_bounds__(256)
void pinn_build_table(const float* __restrict__ gW0, const float* __restrict__ gb0,
                      const float* __restrict__ gW1, const float* __restrict__ gb1,
                      const float* __restrict__ gW2, const float* __restrict__ gb2)
{
    const unsigned FULL = 0xffffffffu;
    int gtid = blockIdx.x * blockDim.x + threadIdx.x;
    int node = gtid >> 3;
    int s    = gtid & 7;                 // this lane's neuron index
    bool live = node < KNODES;
    int nodec = live ? node : KNODES - 1;   // clamp; keep all lanes in shuffles

    const float x0 = (float)nodec * HF;

    // ---- Layer 0 jet for neuron s only ----
    float h0, h1, h2, h3, h4, h5, h6;
    {
        float w = gW0[s];
        float z = fmaf(w, x0, gb0[s]);
        float sg;
        float t = tanh_fast(z, sg);
        float t2 = t * t;
        float d2 = -2.0f * t * sg;
        float d3 = sg * (6.0f * t2 - 2.0f);
        float d4 = t * sg * (16.0f - 24.0f * t2);
        float d5 = sg * (16.0f + t2 * (-120.0f + 120.0f * t2));
        float d6 = sg * t * (-272.0f + t2 * (960.0f - 720.0f * t2));
        float w2 = w * w, w3 = w2 * w;
        h0 = t;
        h1 = sg * w;
        h2 = d2 * w2;
        h3 = d3 * w3;
        h4 = d4 * w2 * w2;
        h5 = d5 * w2 * w3;
        h6 = d6 * w3 * w3;
    }

    // ---- Layer 1 row s: z[m] = b1[s] + sum_k W1[s,k] * h[m] (lane k) ----
    float z0 = gb1[s], z1 = 0.f, z2 = 0.f, z3 = 0.f, z4 = 0.f, z5 = 0.f, z6 = 0.f;
#pragma unroll
    for (int k = 0; k < 8; ++k) {
        float wk = gW1[s * 8 + k];
        z0 = fmaf(wk, __shfl_sync(FULL, h0, k, 8), z0);
        z1 = fmaf(wk, __shfl_sync(FULL, h1, k, 8), z1);
        z2 = fmaf(wk, __shfl_sync(FULL, h2, k, 8), z2);
        z3 = fmaf(wk, __shfl_sync(FULL, h3, k, 8), z3);
        z4 = fmaf(wk, __shfl_sync(FULL, h4, k, 8), z4);
        z5 = fmaf(wk, __shfl_sync(FULL, h5, k, 8), z5);
        z6 = fmaf(wk, __shfl_sync(FULL, h6, k, 8), z6);
    }

    // ---- tanh jet + Faa di Bruno to order 6 for neuron s ----
    float g0, g1, g2, g3, g4, g5, g6;
    {
        float sg;
        float t = tanh_fast(z0, sg);
        float t2 = t * t;
        float d1 = sg;
        float d2 = -2.0f * t * sg;
        float d3 = sg * (6.0f * t2 - 2.0f);
        float d4 = t * sg * (16.0f - 24.0f * t2);
        float d5 = sg * (16.0f + t2 * (-120.0f + 120.0f * t2));
        float d6 = sg * t * (-272.0f + t2 * (960.0f - 720.0f * t2));

        float z1_2 = z1 * z1, z1_3 = z1_2 * z1, z1_4 = z1_2 * z1_2;
        g0 = t;
        g1 = d1 * z1;
        g2 = d1 * z2 + d2 * z1_2;
        g3 = d1 * z3 + 3.0f * d2 * z1 * z2 + d3 * z1_3;
        g4 = d1 * z4 + d2 * (4.0f * z1 * z3 + 3.0f * z2 * z2)
           + 6.0f * d3 * z1_2 * z2 + d4 * z1_4;
        g5 = d1 * z5 + d2 * (5.0f * z1 * z4 + 10.0f * z2 * z3)
           + d3 * (10.0f * z1_2 * z3 + 15.0f * z1 * z2 * z2)
           + 10.0f * d4 * z1_3 * z2 + d5 * z1_4 * z1;
        g6 = d1 * z6 + d2 * (6.0f * z1 * z5 + 15.0f * z2 * z4 + 10.0f * z3 * z3)
           + d3 * (15.0f * z1_2 * z4 + 60.0f * z1 * z2 * z3 + 15.0f * z2 * z2 * z2)
           + d4 * (20.0f * z1_3 * z3 + 45.0f * z1_2 * z2 * z2)
           + 15.0f * d5 * z1_4 * z2 + d6 * z1_4 * z1_2;
    }

    // ---- output taps + butterfly reduce over the octet ----
    float wu = gW2[s], ww = gW2[8 + s];
    float U0 = wu * g0, U1 = wu * g1, U2 = wu * g2, U3 = wu * g3, U4 = wu * g4;
    float V0 = ww * g0, V1 = ww * g1, V2 = ww * g2, V3 = ww * g3,
          V4 = ww * g4, V5 = ww * g5, V6 = ww * g6;
#pragma unroll
    for (int off = 4; off >= 1; off >>= 1) {
        U0 += __shfl_xor_sync(FULL, U0, off, 8);
        U1 += __shfl_xor_sync(FULL, U1, off, 8);
        U2 += __shfl_xor_sync(FULL, U2, off, 8);
        U3 += __shfl_xor_sync(FULL, U3, off, 8);
        U4 += __shfl_xor_sync(FULL, U4, off, 8);
        V0 += __shfl_xor_sync(FULL, V0, off, 8);
        V1 += __shfl_xor_sync(FULL, V1, off, 8);
        V2 += __shfl_xor_sync(FULL, V2, off, 8);
        V3 += __shfl_xor_sync(FULL, V3, off, 8);
        V4 += __shfl_xor_sync(FULL, V4, off, 8);
        V5 += __shfl_xor_sync(FULL, V5, off, 8);
        V6 += __shfl_xor_sync(FULL, V6, off, 8);
    }
    U0 += gb2[0];
    V0 += gb2[1];

    // ---- lane s stores its (val, d1, d2) group ----
    float v0, v1, v2;
    switch (s) {
        case 0: v0 = U0; v1 = U1; v2 = U2; break;
        case 1: v0 = U1; v1 = U2; v2 = U3; break;
        case 2: v0 = U2; v1 = U3; v2 = U4; break;
        case 3: v0 = V0; v1 = V1; v2 = V2; break;
        case 4: v0 = V1; v1 = V2; v2 = V3; break;
        case 5: v0 = V2; v1 = V3; v2 = V4; break;
        case 6: v0 = V3; v1 = V4; v2 = V5; break;
        default: v0 = V4; v1 = V5; v2 = V6; break;
    }
    if (live)
        g_tab8[node * 8 + s] = make_float4(v0, v1, v2, 0.0f);
}

// ---------------- Kernel B: octet-cooperative Taylor interp ----------------

#define IB   256
#define PPQ  4      // passes per warp; warp covers 16 points

__global__ __launch_bounds__(IB)
void pinn_interp(const float* __restrict__ x, float* __restrict__ out, int n)
{
    const int lane = threadIdx.x & 31;
    const int oct  = lane >> 3;               // 0..3
    const int s    = lane & 7;                // output index for this lane
    const int wid  = (blockIdx.x * IB + threadIdx.x) >> 5;
    const int wbase = wid * (4 * PPQ);        // 16 points per warp

    // ---- Phase 1: batched x loads (broadcast within each octet) ----
    float xv[PPQ];
#pragma unroll
    for (int k = 0; k < PPQ; ++k) {
        int p  = wbase + 4 * k + oct;
        int pc = p < n ? p : n - 1;
        xv[k] = __ldg(x + pc);
    }

    // ---- Phase 2: index math + batched table line loads ----
    float dx[PPQ], t2[PPQ];
    int   jn[PPQ];
#pragma unroll
    for (int k = 0; k < PPQ; ++k) {
        float tm = fmaf(xv[k], HINV, MAGIC);
        jn[k] = __float_as_int(tm) & 0x3FF;
        float fj = tm - MAGIC;
        dx[k] = fmaf(fj, -HF, xv[k]);
        t2[k] = 0.5f * dx[k] * dx[k];
    }
    float4 f[PPQ];
#pragma unroll
    for (int k = 0; k < PPQ; ++k)
        f[k] = __ldg(&g_tab8[jn[k] * 8 + s]);

    // ---- Phase 3: 2 FMAs per lane, coalesced STG.32 ----
#pragma unroll
    for (int k = 0; k < PPQ; ++k) {
        float o = fmaf(t2[k], f[k].z, fmaf(dx[k], f[k].y, f[k].x));
        int p = wbase + 4 * k + oct;
        if (p < n)
            out[(size_t)p * 8 + s] = o;
    }
}

extern "C" void kernel_launch(void* const* d_in, const int* in_sizes, int n_in,
                              void* d_out, int out_size)
{
    const float* x  = (const float*)d_in[0];
    const float* W0 = (const float*)d_in[1];
    const float* b0 = (const float*)d_in[2];
    const float* W1 = (const float*)d_in[3];
    const float* b1 = (const float*)d_in[4];
    const float* W2 = (const float*)d_in[5];
    const float* b2 = (const float*)d_in[6];
    float* out = (float*)d_out;

    int n = in_sizes[0];

    int build_threads = KNODES * 8;                       // 4104
    pinn_build_table<<<(build_threads + 255) / 256, 256>>>(W0, b0, W1, b1, W2, b2);

    int pts_per_block = (IB / 32) * 4 * PPQ;              // 128
    int blocks = (n + pts_per_block - 1) / pts_per_block;
    pinn_interp<<<blocks, IB>>>(x, out, n);
}

// round 12
// speedup vs baseline: 1.5195x; 1.2487x over previous
#include <cuda_runtime.h>

// PINN via tabulated jets, quad-cooperative interpolation, 8 pts/quad.
// Table: 513 nodes (h=2^-9), 64B/node in 4 overlapping float4 groups:
//  g0=(u0,u1,u2,u3) g1=(u3,u4,w0,w1) g2=(w1,w2,w3,w4) g3=(w3,w4,w5,w6)
// Kernel A: order-6 jets, 8 threads/node (one per layer-1 neuron).
// Kernel B: 4 lanes/point, one LDG.128 per lane per point, 8 points
// batched per quad for MLP; 2 seam shuffles; coalesced float2 stores.
// Outputs: [u,u_x,u_xx,w,w_x,w_xx,w_xxx,w_xxxx].

#define KNODES 513
#define HINV   512.0f
#define HF     0.001953125f      // 2^-9 exact
#define MAGIC  12582912.0f       // 1.5 * 2^23

__device__ __align__(128) float4 g_tab4[KNODES * 4];

__device__ __forceinline__ float tanh_fast(float z, float& s) {
    float e, r;
    asm("ex2.approx.f32 %0, %1;" : "=f"(e) : "f"(z * 2.8853900817779268f));
    asm("rcp.approx.f32 %0, %1;" : "=f"(r) : "f"(e + 1.0f));
    float t = fmaf(-2.0f, r, 1.0f);
    s = fmaf(-t, t, 1.0f);
    return t;
}

// ---------------- Kernel A: order-6 jets, 8 threads per node ----------------

__global__ __launch_bounds__(256)
void pinn_build_table(const float* __restrict__ gW0, const float* __restrict__ gb0,
                      const float* __restrict__ gW1, const float* __restrict__ gb1,
                      const float* __restrict__ gW2, const float* __restrict__ gb2)
{
    const unsigned FULL = 0xffffffffu;
    int gtid = blockIdx.x * blockDim.x + threadIdx.x;
    int node = gtid >> 3;
    int s    = gtid & 7;
    bool live = node < KNODES;
    int nodec = live ? node : KNODES - 1;

    const float x0 = (float)nodec * HF;

    // Layer 0 jet for neuron s
    float h0, h1, h2, h3, h4, h5, h6;
    {
        float w = gW0[s];
        float z = fmaf(w, x0, gb0[s]);
        float sg;
        float t = tanh_fast(z, sg);
        float t2 = t * t;
        float d2 = -2.0f * t * sg;
        float d3 = sg * (6.0f * t2 - 2.0f);
        float d4 = t * sg * (16.0f - 24.0f * t2);
        float d5 = sg * (16.0f + t2 * (-120.0f + 120.0f * t2));
        float d6 = sg * t * (-272.0f + t2 * (960.0f - 720.0f * t2));
        float w2 = w * w, w3 = w2 * w;
        h0 = t;      h1 = sg * w;  h2 = d2 * w2; h3 = d3 * w3;
        h4 = d4 * w2 * w2; h5 = d5 * w2 * w3; h6 = d6 * w3 * w3;
    }

    // Layer 1 row s via width-8 shuffles
    float z0 = gb1[s], z1 = 0.f, z2 = 0.f, z3 = 0.f, z4 = 0.f, z5 = 0.f, z6 = 0.f;
#pragma unroll
    for (int k = 0; k < 8; ++k) {
        float wk = gW1[s * 8 + k];
        z0 = fmaf(wk, __shfl_sync(FULL, h0, k, 8), z0);
        z1 = fmaf(wk, __shfl_sync(FULL, h1, k, 8), z1);
        z2 = fmaf(wk, __shfl_sync(FULL, h2, k, 8), z2);
        z3 = fmaf(wk, __shfl_sync(FULL, h3, k, 8), z3);
        z4 = fmaf(wk, __shfl_sync(FULL, h4, k, 8), z4);
        z5 = fmaf(wk, __shfl_sync(FULL, h5, k, 8), z5);
        z6 = fmaf(wk, __shfl_sync(FULL, h6, k, 8), z6);
    }

    // tanh jet + Faa di Bruno to order 6
    float g0, g1, g2, g3, g4, g5, g6;
    {
        float sg;
        float t = tanh_fast(z0, sg);
        float t2 = t * t;
        float d1 = sg;
        float d2 = -2.0f * t * sg;
        float d3 = sg * (6.0f * t2 - 2.0f);
        float d4 = t * sg * (16.0f - 24.0f * t2);
        float d5 = sg * (16.0f + t2 * (-120.0f + 120.0f * t2));
        float d6 = sg * t * (-272.0f + t2 * (960.0f - 720.0f * t2));

        float z1_2 = z1 * z1, z1_3 = z1_2 * z1, z1_4 = z1_2 * z1_2;
        g0 = t;
        g1 = d1 * z1;
        g2 = d1 * z2 + d2 * z1_2;
        g3 = d1 * z3 + 3.0f * d2 * z1 * z2 + d3 * z1_3;
        g4 = d1 * z4 + d2 * (4.0f * z1 * z3 + 3.0f * z2 * z2)
           + 6.0f * d3 * z1_2 * z2 + d4 * z1_4;
        g5 = d1 * z5 + d2 * (5.0f * z1 * z4 + 10.0f * z2 * z3)
           + d3 * (10.0f * z1_2 * z3 + 15.0f * z1 * z2 * z2)
           + 10.0f * d4 * z1_3 * z2 + d5 * z1_4 * z1;
        g6 = d1 * z6 + d2 * (6.0f * z1 * z5 + 15.0f * z2 * z4 + 10.0f * z3 * z3)
           + d3 * (15.0f * z1_2 * z4 + 60.0f * z1 * z2 * z3 + 15.0f * z2 * z2 * z2)
           + d4 * (20.0f * z1_3 * z3 + 45.0f * z1_2 * z2 * z2)
           + 15.0f * d5 * z1_4 * z2 + d6 * z1_4 * z1_2;
    }

    // output taps + butterfly reduce over octet
    float wu = gW2[s], ww = gW2[8 + s];
    float U0 = wu * g0, U1 = wu * g1, U2 = wu * g2, U3 = wu * g3, U4 = wu * g4;
    float V0 = ww * g0, V1 = ww * g1, V2 = ww * g2, V3 = ww * g3,
          V4 = ww * g4, V5 = ww * g5, V6 = ww * g6;
#pragma unroll
    for (int off = 4; off >= 1; off >>= 1) {
        U0 += __shfl_xor_sync(FULL, U0, off, 8);
        U1 += __shfl_xor_sync(FULL, U1, off, 8);
        U2 += __shfl_xor_sync(FULL, U2, off, 8);
        U3 += __shfl_xor_sync(FULL, U3, off, 8);
        U4 += __shfl_xor_sync(FULL, U4, off, 8);
        V0 += __shfl_xor_sync(FULL, V0, off, 8);
        V1 += __shfl_xor_sync(FULL, V1, off, 8);
        V2 += __shfl_xor_sync(FULL, V2, off, 8);
        V3 += __shfl_xor_sync(FULL, V3, off, 8);
        V4 += __shfl_xor_sync(FULL, V4, off, 8);
        V5 += __shfl_xor_sync(FULL, V5, off, 8);
        V6 += __shfl_xor_sync(FULL, V6, off, 8);
    }
    U0 += gb2[0];
    V0 += gb2[1];

    // lanes 0..3 write the quad-layout groups
    if (live && s < 4) {
        float4 v;
        switch (s) {
            case 0:  v = make_float4(U0, U1, U2, U3); break;
            case 1:  v = make_float4(U3, U4, V0, V1); break;
            case 2:  v = make_float4(V1, V2, V3, V4); break;
            default: v = make_float4(V3, V4, V5, V6); break;
        }
        g_tab4[node * 4 + s] = v;
    }
}

// ---------------- Kernel B: quad-cooperative, 8 pts/quad, batched ----------

#define IB   256
#define PPQ  8     // points per quad; warp covers 64 points

__global__ __launch_bounds__(IB)
void pinn_interp(const float* __restrict__ x, float* __restrict__ out, int n)
{
    const int lane  = threadIdx.x & 31;
    const int sub   = lane & 3;
    const int lb    = lane & ~3;
    const int quad  = lane >> 2;               // 0..7
    const int wid   = (blockIdx.x * IB + threadIdx.x) >> 5;
    const int wbase = wid * (8 * PPQ);         // 64 points per warp

    // ---- Phase 1: batched x loads ----
    float xv[PPQ];
#pragma unroll
    for (int k = 0; k < PPQ; ++k) {
        int p  = wbase + 8 * k + quad;
        int pc = p < n ? p : n - 1;
        xv[k] = __ldg(x + pc);
    }

    // ---- Phase 2: index math + batched table loads ----
    float dx[PPQ];
    int   jn[PPQ];
#pragma unroll
    for (int k = 0; k < PPQ; ++k) {
        float tm = fmaf(xv[k], HINV, MAGIC);
        jn[k] = __float_as_int(tm) & 0x3FF;
        float fj = tm - MAGIC;
        dx[k] = fmaf(fj, -HF, xv[k]);
    }
    float4 f[PPQ];
#pragma unroll
    for (int k = 0; k < PPQ; ++k)
        f[k] = __ldg(&g_tab4[jn[k] * 4 + sub]);

    // ---- Phase 3: seam shuffles, Taylor, coalesced stores ----
#pragma unroll
    for (int k = 0; k < PPQ; ++k) {
        float t2 = 0.5f * dx[k] * dx[k];
        float sz = __shfl_sync(0xffffffffu, f[k].z, lb);      // u2 from sub0
        float sy = __shfl_sync(0xffffffffu, f[k].y, lb + 2);  // w2 from sub2

        float oA, oB;
        if (sub == 1) {
            oA = fmaf(t2, f[k].y, fmaf(dx[k], f[k].x, sz));     // u_xx
            oB = fmaf(t2, sy,     fmaf(dx[k], f[k].w, f[k].z)); // w
        } else {
            oA = fmaf(t2, f[k].z, fmaf(dx[k], f[k].y, f[k].x));
            oB = fmaf(t2, f[k].w, fmaf(dx[k], f[k].z, f[k].y));
        }

        int p = wbase + 8 * k + quad;
        if (p < n) {
            float2* op = reinterpret_cast<float2*>(out + (size_t)p * 8) + sub;
            *op = make_float2(oA, oB);
        }
    }
}

extern "C" void kernel_launch(void* const* d_in, const int* in_sizes, int n_in,
                              void* d_out, int out_size)
{
    const float* x  = (const float*)d_in[0];
    const float* W0 = (const float*)d_in[1];
    const float* b0 = (const float*)d_in[2];
    const float* W1 = (const float*)d_in[3];
    const float* b1 = (const float*)d_in[4];
    const float* W2 = (const float*)d_in[5];
    const float* b2 = (const float*)d_in[6];
    float* out = (float*)d_out;

    int n = in_sizes[0];

    int build_threads = KNODES * 8;   // 4104
    pinn_build_table<<<(build_threads + 255) / 256, 256>>>(W0, b0, W1, b1, W2, b2);

    int pts_per_block = (IB / 32) * 8 * PPQ;   // 512 points per block
    int blocks = (n + pts_per_block - 1) / pts_per_block;
    pinn_interp<<<blocks, IB>>>(x, out, n);
}